// round 1
// baseline (speedup 1.0000x reference)
#include <cuda_runtime.h>
#include <math.h>

// ---------------- problem constants ----------------
#define NL   12
#define NH   12
#define DM   768
#define DFF  3072
#define NV   100256
#define DH   64
#define NB   2
#define NT   1024
#define MROWS (NB*NT)          // 2048

// ---------------- scratch (device globals; no allocs allowed) ----------------
__device__ float g_x  [MROWS*DM];
__device__ float g_h  [MROWS*DM];
__device__ float g_q  [MROWS*DM];
__device__ float g_k  [MROWS*DM];
__device__ float g_v  [MROWS*DM];
__device__ float g_att[MROWS*DM];
__device__ float g_ff [MROWS*DFF];
__device__ float g_rowloss[MROWS];

// ---------------- embedding + sinusoidal positional encoding ----------------
__global__ void embed_kernel(const int* __restrict__ idx,
                             const float* __restrict__ emb,
                             float* __restrict__ x)
{
    int i = blockIdx.x * blockDim.x + threadIdx.x;
    if (i >= MROWS * DM) return;
    int d  = i % DM;
    int bt = i / DM;
    int t  = bt % NT;
    int tok = idx[bt];
    int ii = d & ~1;                     // even index of the (sin,cos) pair
    float div = expf(-(float)ii * (logf(10000.0f) / (float)DM));
    float ang = (float)t * div;
    float pe  = (d & 1) ? cosf(ang) : sinf(ang);
    x[i] = emb[(size_t)tok * DM + d] + pe;
}

// ---------------- layernorm (two-pass exact, 768 = 3*256) ----------------
__global__ void ln_kernel(const float* __restrict__ x,
                          const float* __restrict__ s,
                          const float* __restrict__ b,
                          float* __restrict__ y)
{
    int row = blockIdx.x;
    int tid = threadIdx.x;
    const float* xr = x + (size_t)row * DM;

    float v0 = xr[tid], v1 = xr[tid + 256], v2 = xr[tid + 512];

    __shared__ float red[256];
    float lsum = v0 + v1 + v2;
    red[tid] = lsum; __syncthreads();
    for (int o = 128; o > 0; o >>= 1) {
        if (tid < o) red[tid] += red[tid + o];
        __syncthreads();
    }
    float mu = red[0] * (1.0f / DM);
    __syncthreads();

    float d0 = v0 - mu, d1 = v1 - mu, d2 = v2 - mu;
    red[tid] = d0*d0 + d1*d1 + d2*d2; __syncthreads();
    for (int o = 128; o > 0; o >>= 1) {
        if (tid < o) red[tid] += red[tid + o];
        __syncthreads();
    }
    float var = red[0] * (1.0f / DM);
    float r = rsqrtf(var + 1e-5f);

    float* yr = y + (size_t)row * DM;
    yr[tid      ] = d0 * r * s[tid      ] + b[tid      ];
    yr[tid + 256] = d1 * r * s[tid + 256] + b[tid + 256];
    yr[tid + 512] = d2 * r * s[tid + 512] + b[tid + 512];
}

// ---------------- SGEMM: C = epilogue(A[MxK] @ B[KxN] + bias [+ R]) ----------
// EPI: 0 = +bias ; 1 = relu(+bias) ; 2 = +bias + residual R
// 128x128 block tile, BK=8, 8x8 per-thread micro tile, 256 threads.
// Requires M % 128 == 0, K % 8 == 0, N % 4 == 0 (all true here).
template<int EPI>
__global__ void __launch_bounds__(256)
sgemm_kernel(const float* __restrict__ A, const float* __restrict__ Bm,
             const float* __restrict__ bias, const float* __restrict__ R,
             float* __restrict__ C, int M, int N, int K)
{
    __shared__ float As[8][128];
    __shared__ float Bs[8][128];

    int tid  = threadIdx.x;
    int row0 = blockIdx.y * 128;
    int col0 = blockIdx.x * 128;

    int arow = tid >> 1;            // 0..127
    int acol = (tid & 1) * 4;       // 0 or 4
    int brow = tid >> 5;            // 0..7
    int bcol = (tid & 31) * 4;      // 0..124

    float acc[8][8];
#pragma unroll
    for (int i = 0; i < 8; i++)
#pragma unroll
        for (int j = 0; j < 8; j++) acc[i][j] = 0.0f;

    const float* Aptr = A + (size_t)(row0 + arow) * K + acol;
    int ty = tid >> 4, tx = tid & 15;

    for (int k0 = 0; k0 < K; k0 += 8) {
        float4 av = *(const float4*)(Aptr + k0);
        As[acol + 0][arow] = av.x;
        As[acol + 1][arow] = av.y;
        As[acol + 2][arow] = av.z;
        As[acol + 3][arow] = av.w;

        int gcol = col0 + bcol;
        float4 bv = make_float4(0.f, 0.f, 0.f, 0.f);
        if (gcol < N)
            bv = *(const float4*)(Bm + (size_t)(k0 + brow) * N + gcol);
        Bs[brow][bcol + 0] = bv.x;
        Bs[brow][bcol + 1] = bv.y;
        Bs[brow][bcol + 2] = bv.z;
        Bs[brow][bcol + 3] = bv.w;

        __syncthreads();

#pragma unroll
        for (int kk = 0; kk < 8; kk++) {
            float ra[8], rb[8];
#pragma unroll
            for (int i = 0; i < 8; i++) ra[i] = As[kk][ty * 8 + i];
#pragma unroll
            for (int j = 0; j < 8; j++) rb[j] = Bs[kk][tx * 8 + j];
#pragma unroll
            for (int i = 0; i < 8; i++)
#pragma unroll
                for (int j = 0; j < 8; j++)
                    acc[i][j] = fmaf(ra[i], rb[j], acc[i][j]);
        }
        __syncthreads();
    }

#pragma unroll
    for (int i = 0; i < 8; i++) {
        int r = row0 + ty * 8 + i;
#pragma unroll
        for (int j = 0; j < 8; j++) {
            int c = col0 + tx * 8 + j;
            if (c < N) {
                float v = acc[i][j];
                if (bias) v += bias[c];
                if (EPI == 1) v = fmaxf(v, 0.0f);
                if (EPI == 2) v += R[(size_t)r * N + c];
                C[(size_t)r * N + c] = v;
            }
        }
    }
}

// ---------------- causal attention: one warp per query row -------------------
// q,k,v,o layout: [B,T,H,DH] flattened — identical to concat-heads layout.
__global__ void attn_kernel(const float* __restrict__ q,
                            const float* __restrict__ k,
                            const float* __restrict__ v,
                            float* __restrict__ o)
{
    int w    = (blockIdx.x * blockDim.x + threadIdx.x) >> 5;
    int lane = threadIdx.x & 31;
    int t = w % NT;
    int h = (w / NT) % NH;
    int b = w / (NT * NH);

    size_t qb = ((size_t)(b * NT + t) * NH + h) * DH;
    float q0 = q[qb + lane];
    float q1 = q[qb + lane + 32];

    float m = -INFINITY, l = 0.0f, o0 = 0.0f, o1 = 0.0f;
    const float scale = 0.125f;   // 1/sqrt(64)

    for (int s = 0; s <= t; s++) {
        size_t kb = ((size_t)(b * NT + s) * NH + h) * DH;
        float d = q0 * k[kb + lane] + q1 * k[kb + lane + 32];
#pragma unroll
        for (int off = 16; off > 0; off >>= 1)
            d += __shfl_xor_sync(0xffffffff, d, off);
        d *= scale;

        float mn = fmaxf(m, d);
        float c  = __expf(m - mn);   // exp(-inf)=0 handles first iter
        float p  = __expf(d - mn);
        l  = l * c + p;
        o0 = o0 * c + p * v[kb + lane];
        o1 = o1 * c + p * v[kb + lane + 32];
        m = mn;
    }
    float inv = 1.0f / l;
    o[qb + lane]      = o0 * inv;
    o[qb + lane + 32] = o1 * inv;
}

// ---------------- per-row NLL loss (single online pass over V) ---------------
__global__ void loss_row_kernel(const float* __restrict__ logits,
                                const int* __restrict__ tgt,
                                float* __restrict__ rowloss)
{
    int r   = blockIdx.x;
    int tid = threadIdx.x;
    const float* lr = logits + (size_t)r * NV;

    float m = -INFINITY, s = 0.0f;
    for (int i = tid; i < NV; i += 256) {
        float x = lr[i];
        if (x > m) { s = s * __expf(m - x) + 1.0f; m = x; }
        else       { s += __expf(x - m); }
    }
    __shared__ float sm[256], ss[256];
    sm[tid] = m; ss[tid] = s; __syncthreads();
    for (int o = 128; o > 0; o >>= 1) {
        if (tid < o) {
            float m2 = sm[tid + o], s2 = ss[tid + o];
            float mn = fmaxf(sm[tid], m2);
            ss[tid] = ss[tid] * __expf(sm[tid] - mn) + s2 * __expf(m2 - mn);
            sm[tid] = mn;
        }
        __syncthreads();
    }
    if (tid == 0) {
        float lse = sm[0] + logf(ss[0]);
        rowloss[r] = lse - lr[tgt[r]];
    }
}

__global__ void loss_reduce_kernel(const float* __restrict__ rowloss,
                                   float* __restrict__ out)
{
    __shared__ float sh[256];
    int tid = threadIdx.x;
    float s = 0.0f;
    for (int i = tid; i < MROWS; i += 256) s += rowloss[i];
    sh[tid] = s; __syncthreads();
    for (int o = 128; o > 0; o >>= 1) {
        if (tid < o) sh[tid] += sh[tid + o];
        __syncthreads();
    }
    if (tid == 0) out[0] = sh[0] * (1.0f / MROWS);
}

// ---------------- host driver ----------------
static inline dim3 gemm_grid(int M, int N) {
    return dim3((N + 127) / 128, (M + 127) / 128);
}

extern "C" void kernel_launch(void* const* d_in, const int* in_sizes, int n_in,
                              void* d_out, int out_size)
{
    const int*   idx     = (const int*)  d_in[0];
    const int*   targets = (const int*)  d_in[1];
    const float* emb     = (const float*)d_in[2];
    const float* wq      = (const float*)d_in[3];
    const float* wk      = (const float*)d_in[4];
    const float* wv      = (const float*)d_in[5];
    const float* wo      = (const float*)d_in[6];
    const float* bo      = (const float*)d_in[7];
    const float* ln1_s   = (const float*)d_in[8];
    const float* ln1_b   = (const float*)d_in[9];
    const float* ln2_s   = (const float*)d_in[10];
    const float* ln2_b   = (const float*)d_in[11];
    const float* w1      = (const float*)d_in[12];
    const float* b1      = (const float*)d_in[13];
    const float* w2      = (const float*)d_in[14];
    const float* b2      = (const float*)d_in[15];
    const float* lnf_s   = (const float*)d_in[16];
    const float* lnf_b   = (const float*)d_in[17];
    const float* w_out   = (const float*)d_in[18];
    const float* b_out   = (const float*)d_in[19];
    float* out = (float*)d_out;

    float *x, *h, *q, *k, *v, *att, *ff, *rl;
    cudaGetSymbolAddress((void**)&x,   g_x);
    cudaGetSymbolAddress((void**)&h,   g_h);
    cudaGetSymbolAddress((void**)&q,   g_q);
    cudaGetSymbolAddress((void**)&k,   g_k);
    cudaGetSymbolAddress((void**)&v,   g_v);
    cudaGetSymbolAddress((void**)&att, g_att);
    cudaGetSymbolAddress((void**)&ff,  g_ff);
    cudaGetSymbolAddress((void**)&rl,  g_rowloss);

    // x = emb[idx] + PE
    embed_kernel<<<(MROWS * DM + 255) / 256, 256>>>(idx, emb, x);

    for (int l = 0; l < NL; l++) {
        const float* wql = wq + (size_t)l * DM * DM;
        const float* wkl = wk + (size_t)l * DM * DM;
        const float* wvl = wv + (size_t)l * DM * DM;
        const float* wol = wo + (size_t)l * DM * DM;
        const float* w1l = w1 + (size_t)l * DM * DFF;
        const float* w2l = w2 + (size_t)l * DFF * DM;

        // h = LN1(x)
        ln_kernel<<<MROWS, 256>>>(x, ln1_s + l * DM, ln1_b + l * DM, h);

        // q,k,v = h @ w{q,k,v}
        sgemm_kernel<0><<<gemm_grid(MROWS, DM), 256>>>(h, wql, nullptr, nullptr, q, MROWS, DM, DM);
        sgemm_kernel<0><<<gemm_grid(MROWS, DM), 256>>>(h, wkl, nullptr, nullptr, k, MROWS, DM, DM);
        sgemm_kernel<0><<<gemm_grid(MROWS, DM), 256>>>(h, wvl, nullptr, nullptr, v, MROWS, DM, DM);

        // att = causal_softmax(qk^T/8) v   (concat-heads layout by construction)
        attn_kernel<<<(MROWS * NH) / 8, 256>>>(q, k, v, att);

        // x = x + att @ wo + bo
        sgemm_kernel<2><<<gemm_grid(MROWS, DM), 256>>>(att, wol, bo + l * DM, x, x, MROWS, DM, DM);

        // h = LN2(x)
        ln_kernel<<<MROWS, 256>>>(x, ln2_s + l * DM, ln2_b + l * DM, h);

        // ff = relu(h @ w1 + b1)
        sgemm_kernel<1><<<gemm_grid(MROWS, DFF), 256>>>(h, w1l, b1 + l * DFF, nullptr, ff, MROWS, DFF, DM);

        // x = x + ff @ w2 + b2
        sgemm_kernel<2><<<gemm_grid(MROWS, DM), 256>>>(ff, w2l, b2 + l * DM, x, x, MROWS, DM, DFF);
    }

    // h = LNf(x)
    ln_kernel<<<MROWS, 256>>>(x, lnf_s, lnf_b, h);

    // logits = h @ w_out + b_out  -> d_out[0 .. B*T*V)
    sgemm_kernel<0><<<gemm_grid(MROWS, NV), 256>>>(h, w_out, b_out, nullptr, out, MROWS, NV, DM);

    // loss -> d_out[B*T*V]
    loss_row_kernel<<<MROWS, 256>>>(out, targets, rl);
    loss_reduce_kernel<<<1, 256>>>(rl, out + (size_t)MROWS * NV);
}

// round 2
// speedup vs baseline: 1.5095x; 1.5095x over previous
#include <cuda_runtime.h>
#include <math.h>
#include <stdint.h>

// ---------------- problem constants ----------------
#define NL   12
#define NH   12
#define DM   768
#define DFF  3072
#define NV   100256
#define DH   64
#define NB   2
#define NT   1024
#define MROWS (NB*NT)          // 2048

// ---------------- scratch (device globals; no allocs allowed) ----------------
__device__ float g_x  [MROWS*DM];
__device__ float g_h  [MROWS*DM];
__device__ float g_q  [MROWS*DM];
__device__ float g_k  [MROWS*DM];
__device__ float g_v  [MROWS*DM];
__device__ float g_att[MROWS*DM];
__device__ float g_ff [MROWS*DFF];
__device__ float g_rowloss[MROWS];

// ---------------- small PTX helpers ----------------
__device__ __forceinline__ unsigned cvt_tf32(float x) {
    unsigned r;
    asm("cvt.rna.tf32.f32 %0, %1;" : "=r"(r) : "f"(x));
    return r;
}
__device__ __forceinline__ void split_tf32(float x, unsigned& hi, unsigned& lo) {
    hi = cvt_tf32(x);
    lo = cvt_tf32(x - __uint_as_float(hi));
}
__device__ __forceinline__ void mma_tf32(float* d, const unsigned* a, const unsigned* b) {
    asm volatile(
        "mma.sync.aligned.m16n8k8.row.col.f32.tf32.tf32.f32 "
        "{%0,%1,%2,%3}, {%4,%5,%6,%7}, {%8,%9}, {%0,%1,%2,%3};\n"
        : "+f"(d[0]), "+f"(d[1]), "+f"(d[2]), "+f"(d[3])
        : "r"(a[0]), "r"(a[1]), "r"(a[2]), "r"(a[3]), "r"(b[0]), "r"(b[1]));
}
__device__ __forceinline__ void cpasync16(unsigned dst, const void* src, int srcbytes) {
    asm volatile("cp.async.cg.shared.global [%0], [%1], 16, %2;"
                 :: "r"(dst), "l"(src), "r"(srcbytes));
}

// ---------------- embedding + sinusoidal positional encoding ----------------
__global__ void embed_kernel(const int* __restrict__ idx,
                             const float* __restrict__ emb,
                             float* __restrict__ x)
{
    int i = blockIdx.x * blockDim.x + threadIdx.x;
    if (i >= MROWS * DM) return;
    int d  = i % DM;
    int bt = i / DM;
    int t  = bt % NT;
    int tok = idx[bt];
    int ii = d & ~1;
    float div = expf(-(float)ii * (logf(10000.0f) / (float)DM));
    float ang = (float)t * div;
    float pe  = (d & 1) ? cosf(ang) : sinf(ang);
    x[i] = emb[(size_t)tok * DM + d] + pe;
}

// ---------------- layernorm (two-pass exact, 768 = 3*256) ----------------
__global__ void ln_kernel(const float* __restrict__ x,
                          const float* __restrict__ s,
                          const float* __restrict__ b,
                          float* __restrict__ y)
{
    int row = blockIdx.x;
    int tid = threadIdx.x;
    const float* xr = x + (size_t)row * DM;

    float v0 = xr[tid], v1 = xr[tid + 256], v2 = xr[tid + 512];

    __shared__ float red[256];
    red[tid] = v0 + v1 + v2; __syncthreads();
    for (int o = 128; o > 0; o >>= 1) {
        if (tid < o) red[tid] += red[tid + o];
        __syncthreads();
    }
    float mu = red[0] * (1.0f / DM);
    __syncthreads();

    float d0 = v0 - mu, d1 = v1 - mu, d2 = v2 - mu;
    red[tid] = d0*d0 + d1*d1 + d2*d2; __syncthreads();
    for (int o = 128; o > 0; o >>= 1) {
        if (tid < o) red[tid] += red[tid + o];
        __syncthreads();
    }
    float var = red[0] * (1.0f / DM);
    float r = rsqrtf(var + 1e-5f);

    float* yr = y + (size_t)row * DM;
    yr[tid      ] = d0 * r * s[tid      ] + b[tid      ];
    yr[tid + 256] = d1 * r * s[tid + 256] + b[tid + 256];
    yr[tid + 512] = d2 * r * s[tid + 512] + b[tid + 512];
}

// ---------------- tensor-core GEMM (3xTF32 split ~ fp32 accuracy) -----------
// C = epilogue(A[MxK] @ B[KxN] + bias [+ R])
// EPI: 0 = +bias ; 1 = relu(+bias) ; 2 = +bias + residual R (R may alias C)
// Block tile 128 x BN, BK=16, 256 threads (8 warps).
// blockIdx.z selects one of up to 3 (B, C, bias) triples (fused QKV).
struct BPtrs {
    const float* B[3];
    float*       C[3];
    const float* bias[3];
};

template<int BN, int MT, int NTT, int EPI>
__global__ void __launch_bounds__(256)
mma_gemm(const float* __restrict__ A, BPtrs p, const float* __restrict__ R,
         int M, int N, int K)
{
    constexpr int BM = 128, BK = 16;
    constexpr int AP = 20;          // As row pad (floats) -> conflict-free frags
    constexpr int BP = BN + 8;      // Bs row pad
    constexpr int WCOLS = BN / (NTT * 8);

    __shared__ float As[2][BM * AP];
    __shared__ float Bs[2][BK * BP];

    const int z = blockIdx.z;
    const float* __restrict__ Bm   = p.B[z];
    float*       __restrict__ C    = p.C[z];
    const float* __restrict__ bias = p.bias[z];

    const int tid  = threadIdx.x;
    const int lane = tid & 31;
    const int w    = tid >> 5;
    const int wm   = w / WCOLS;
    const int wn   = w % WCOLS;
    const int row0 = blockIdx.y * BM;
    const int col0 = blockIdx.x * BN;
    const int grp  = lane >> 2;      // 0..7
    const int tig  = lane & 3;       // 0..3
    const int mB   = wm * MT * 16;
    const int nB   = wn * NTT * 8;

    float acc[MT][NTT][4];
#pragma unroll
    for (int i = 0; i < MT; i++)
#pragma unroll
        for (int j = 0; j < NTT; j++)
#pragma unroll
            for (int q = 0; q < 4; q++) acc[i][j][q] = 0.0f;

    auto load_stage = [&](int buf, int k0) {
        unsigned asb = (unsigned)__cvta_generic_to_shared(&As[buf][0]);
#pragma unroll
        for (int j = 0; j < 2; j++) {
            int ch = tid + j * 256;              // 512 chunks of 16B
            int m  = ch >> 2;
            int kq = (ch & 3) * 4;
            cpasync16(asb + (unsigned)(m * AP + kq) * 4,
                      A + (size_t)(row0 + m) * K + k0 + kq, 16);
        }
        unsigned bsb = (unsigned)__cvta_generic_to_shared(&Bs[buf][0]);
        constexpr int BCH = BK * BN / 4;         // 512 (BN=128) or 256 (BN=64)
#pragma unroll
        for (int j = 0; j < BCH / 256; j++) {
            int ch = tid + j * 256;
            int kk = ch / (BN / 4);
            int nq = (ch % (BN / 4)) * 4;
            int gc = col0 + nq;
            int ok = (gc < N) ? 16 : 0;
            int gcs = (gc < N) ? gc : (N - 4);   // clamp addr, zero-fill OOB
            cpasync16(bsb + (unsigned)(kk * BP + nq) * 4,
                      Bm + (size_t)(k0 + kk) * N + gcs, ok);
        }
    };

    auto compute_stage = [&](int buf) {
        const float* __restrict__ as = &As[buf][0];
        const float* __restrict__ bs = &Bs[buf][0];
#pragma unroll
        for (int ks = 0; ks < 2; ks++) {
            unsigned bhi[NTT][2], blo[NTT][2];
#pragma unroll
            for (int nt = 0; nt < NTT; nt++) {
#pragma unroll
                for (int jj = 0; jj < 2; jj++) {
                    float br = bs[(ks * 8 + tig + jj * 4) * BP + nB + nt * 8 + grp];
                    split_tf32(br, bhi[nt][jj], blo[nt][jj]);
                }
            }
#pragma unroll
            for (int mt = 0; mt < MT; mt++) {
                int r = mB + mt * 16 + grp;
                float a0 = as[ r      * AP + ks * 8 + tig    ];
                float a1 = as[(r + 8) * AP + ks * 8 + tig    ];
                float a2 = as[ r      * AP + ks * 8 + tig + 4];
                float a3 = as[(r + 8) * AP + ks * 8 + tig + 4];
                unsigned ahi[4], alo[4];
                split_tf32(a0, ahi[0], alo[0]);
                split_tf32(a1, ahi[1], alo[1]);
                split_tf32(a2, ahi[2], alo[2]);
                split_tf32(a3, ahi[3], alo[3]);
#pragma unroll
                for (int nt = 0; nt < NTT; nt++) {
                    mma_tf32(acc[mt][nt], alo, bhi[nt]);   // lo*hi
                    mma_tf32(acc[mt][nt], ahi, blo[nt]);   // hi*lo
                    mma_tf32(acc[mt][nt], ahi, bhi[nt]);   // hi*hi
                }
            }
        }
    };

    const int NKIT = K / BK;
    load_stage(0, 0);
    asm volatile("cp.async.commit_group;");

    for (int it = 0; it < NKIT; ++it) {
        if (it + 1 < NKIT) {
            load_stage((it + 1) & 1, (it + 1) * BK);
            asm volatile("cp.async.commit_group;");
            asm volatile("cp.async.wait_group 1;");
        } else {
            asm volatile("cp.async.wait_group 0;");
        }
        __syncthreads();
        compute_stage(it & 1);
        __syncthreads();
    }

    // epilogue
#pragma unroll
    for (int mt = 0; mt < MT; mt++) {
        int r = row0 + mB + mt * 16 + grp;
#pragma unroll
        for (int nt = 0; nt < NTT; nt++) {
            int c = col0 + nB + nt * 8 + tig * 2;
            if (c < N) {
                float x0 = acc[mt][nt][0], x1 = acc[mt][nt][1];
                float x2 = acc[mt][nt][2], x3 = acc[mt][nt][3];
                if (bias) {
                    float b0 = bias[c], b1 = bias[c + 1];
                    x0 += b0; x1 += b1; x2 += b0; x3 += b1;
                }
                if (EPI == 1) {
                    x0 = fmaxf(x0, 0.f); x1 = fmaxf(x1, 0.f);
                    x2 = fmaxf(x2, 0.f); x3 = fmaxf(x3, 0.f);
                }
                if (EPI == 2) {
                    x0 += R[(size_t) r      * N + c    ];
                    x1 += R[(size_t) r      * N + c + 1];
                    x2 += R[(size_t)(r + 8) * N + c    ];
                    x3 += R[(size_t)(r + 8) * N + c + 1];
                }
                C[(size_t) r      * N + c    ] = x0;
                C[(size_t) r      * N + c + 1] = x1;
                C[(size_t)(r + 8) * N + c    ] = x2;
                C[(size_t)(r + 8) * N + c + 1] = x3;
            }
        }
    }
}

// ---------------- causal attention: one warp per query row -------------------
__global__ void attn_kernel(const float* __restrict__ q,
                            const float* __restrict__ k,
                            const float* __restrict__ v,
                            float* __restrict__ o)
{
    int w    = (blockIdx.x * blockDim.x + threadIdx.x) >> 5;
    int lane = threadIdx.x & 31;
    int t = w % NT;
    int h = (w / NT) % NH;
    int b = w / (NT * NH);

    size_t qb = ((size_t)(b * NT + t) * NH + h) * DH;
    float q0 = q[qb + lane];
    float q1 = q[qb + lane + 32];

    float m = -INFINITY, l = 0.0f, o0 = 0.0f, o1 = 0.0f;
    const float scale = 0.125f;

    for (int s = 0; s <= t; s++) {
        size_t kb = ((size_t)(b * NT + s) * NH + h) * DH;
        float d = q0 * k[kb + lane] + q1 * k[kb + lane + 32];
#pragma unroll
        for (int off = 16; off > 0; off >>= 1)
            d += __shfl_xor_sync(0xffffffff, d, off);
        d *= scale;

        float mn = fmaxf(m, d);
        float c  = __expf(m - mn);
        float p  = __expf(d - mn);
        l  = l * c + p;
        o0 = o0 * c + p * v[kb + lane];
        o1 = o1 * c + p * v[kb + lane + 32];
        m = mn;
    }
    float inv = 1.0f / l;
    o[qb + lane]      = o0 * inv;
    o[qb + lane + 32] = o1 * inv;
}

// ---------------- per-row NLL loss ----------------
__global__ void loss_row_kernel(const float* __restrict__ logits,
                                const int* __restrict__ tgt,
                                float* __restrict__ rowloss)
{
    int r   = blockIdx.x;
    int tid = threadIdx.x;
    const float* lr = logits + (size_t)r * NV;

    float m = -INFINITY, s = 0.0f;
    for (int i = tid; i < NV; i += 256) {
        float x = lr[i];
        if (x > m) { s = s * __expf(m - x) + 1.0f; m = x; }
        else       { s += __expf(x - m); }
    }
    __shared__ float sm[256], ss[256];
    sm[tid] = m; ss[tid] = s; __syncthreads();
    for (int o = 128; o > 0; o >>= 1) {
        if (tid < o) {
            float m2 = sm[tid + o], s2 = ss[tid + o];
            float mn = fmaxf(sm[tid], m2);
            ss[tid] = ss[tid] * __expf(sm[tid] - mn) + s2 * __expf(m2 - mn);
            sm[tid] = mn;
        }
        __syncthreads();
    }
    if (tid == 0) {
        float lse = sm[0] + logf(ss[0]);
        rowloss[r] = lse - lr[tgt[r]];
    }
}

__global__ void loss_reduce_kernel(const float* __restrict__ rowloss,
                                   float* __restrict__ out)
{
    __shared__ float sh[256];
    int tid = threadIdx.x;
    float s = 0.0f;
    for (int i = tid; i < MROWS; i += 256) s += rowloss[i];
    sh[tid] = s; __syncthreads();
    for (int o = 128; o > 0; o >>= 1) {
        if (tid < o) sh[tid] += sh[tid + o];
        __syncthreads();
    }
    if (tid == 0) out[0] = sh[0] * (1.0f / MROWS);
}

// ---------------- host driver ----------------
extern "C" void kernel_launch(void* const* d_in, const int* in_sizes, int n_in,
                              void* d_out, int out_size)
{
    const int*   idx     = (const int*)  d_in[0];
    const int*   targets = (const int*)  d_in[1];
    const float* emb     = (const float*)d_in[2];
    const float* wq      = (const float*)d_in[3];
    const float* wk      = (const float*)d_in[4];
    const float* wv      = (const float*)d_in[5];
    const float* wo      = (const float*)d_in[6];
    const float* bo      = (const float*)d_in[7];
    const float* ln1_s   = (const float*)d_in[8];
    const float* ln1_b   = (const float*)d_in[9];
    const float* ln2_s   = (const float*)d_in[10];
    const float* ln2_b   = (const float*)d_in[11];
    const float* w1      = (const float*)d_in[12];
    const float* b1      = (const float*)d_in[13];
    const float* w2      = (const float*)d_in[14];
    const float* b2      = (const float*)d_in[15];
    const float* lnf_s   = (const float*)d_in[16];
    const float* lnf_b   = (const float*)d_in[17];
    const float* w_out   = (const float*)d_in[18];
    const float* b_out   = (const float*)d_in[19];
    float* out = (float*)d_out;

    float *x, *h, *q, *k, *v, *att, *ff, *rl;
    cudaGetSymbolAddress((void**)&x,   g_x);
    cudaGetSymbolAddress((void**)&h,   g_h);
    cudaGetSymbolAddress((void**)&q,   g_q);
    cudaGetSymbolAddress((void**)&k,   g_k);
    cudaGetSymbolAddress((void**)&v,   g_v);
    cudaGetSymbolAddress((void**)&att, g_att);
    cudaGetSymbolAddress((void**)&ff,  g_ff);
    cudaGetSymbolAddress((void**)&rl,  g_rowloss);

    embed_kernel<<<(MROWS * DM + 255) / 256, 256>>>(idx, emb, x);

    for (int l = 0; l < NL; l++) {
        const float* wql = wq + (size_t)l * DM * DM;
        const float* wkl = wk + (size_t)l * DM * DM;
        const float* wvl = wv + (size_t)l * DM * DM;
        const float* wol = wo + (size_t)l * DM * DM;
        const float* w1l = w1 + (size_t)l * DM * DFF;
        const float* w2l = w2 + (size_t)l * DFF * DM;

        // h = LN1(x)
        ln_kernel<<<MROWS, 256>>>(x, ln1_s + l * DM, ln1_b + l * DM, h);

        // q,k,v = h @ w{q,k,v}   (fused: blockIdx.z selects the matrix)
        {
            BPtrs p;
            p.B[0] = wql; p.B[1] = wkl; p.B[2] = wvl;
            p.C[0] = q;   p.C[1] = k;   p.C[2] = v;
            p.bias[0] = p.bias[1] = p.bias[2] = nullptr;
            mma_gemm<64, 2, 4, 0><<<dim3(DM / 64, MROWS / 128, 3), 256>>>(
                h, p, nullptr, MROWS, DM, DM);
        }

        // att = causal_softmax(q k^T / 8) v
        attn_kernel<<<(MROWS * NH) / 8, 256>>>(q, k, v, att);

        // x = x + att @ wo + bo
        {
            BPtrs p;
            p.B[0] = wol; p.C[0] = x; p.bias[0] = bo + l * DM;
            p.B[1] = p.B[2] = nullptr; p.C[1] = p.C[2] = nullptr;
            p.bias[1] = p.bias[2] = nullptr;
            mma_gemm<64, 2, 4, 2><<<dim3(DM / 64, MROWS / 128, 1), 256>>>(
                att, p, x, MROWS, DM, DM);
        }

        // h = LN2(x)
        ln_kernel<<<MROWS, 256>>>(x, ln2_s + l * DM, ln2_b + l * DM, h);

        // ff = relu(h @ w1 + b1)
        {
            BPtrs p;
            p.B[0] = w1l; p.C[0] = ff; p.bias[0] = b1 + l * DFF;
            p.B[1] = p.B[2] = nullptr; p.C[1] = p.C[2] = nullptr;
            p.bias[1] = p.bias[2] = nullptr;
            mma_gemm<128, 4, 4, 1><<<dim3(DFF / 128, MROWS / 128, 1), 256>>>(
                h, p, nullptr, MROWS, DFF, DM);
        }

        // x = x + ff @ w2 + b2
        {
            BPtrs p;
            p.B[0] = w2l; p.C[0] = x; p.bias[0] = b2 + l * DM;
            p.B[1] = p.B[2] = nullptr; p.C[1] = p.C[2] = nullptr;
            p.bias[1] = p.bias[2] = nullptr;
            mma_gemm<64, 2, 4, 2><<<dim3(DM / 64, MROWS / 128, 1), 256>>>(
                ff, p, x, MROWS, DM, DFF);
        }
    }

    // h = LNf(x)
    ln_kernel<<<MROWS, 256>>>(x, lnf_s, lnf_b, h);

    // logits = h @ w_out + b_out
    {
        BPtrs p;
        p.B[0] = w_out; p.C[0] = out; p.bias[0] = b_out;
        p.B[1] = p.B[2] = nullptr; p.C[1] = p.C[2] = nullptr;
        p.bias[1] = p.bias[2] = nullptr;
        mma_gemm<128, 4, 4, 0><<<dim3((NV + 127) / 128, MROWS / 128, 1), 256>>>(
            h, p, nullptr, MROWS, NV, DM);
    }

    // loss
    loss_row_kernel<<<MROWS, 256>>>(out, targets, rl);
    loss_reduce_kernel<<<1, 256>>>(rl, out + (size_t)MROWS * NV);
}

// round 3
// speedup vs baseline: 1.8663x; 1.2364x over previous
#include <cuda_runtime.h>
#include <cuda_bf16.h>
#include <math.h>
#include <stdint.h>

// ---------------- problem constants ----------------
#define NL   12
#define NH   12
#define DM   768
#define DFF  3072
#define NV   100256
#define DH   64
#define NB   2
#define NT   1024
#define MROWS (NB*NT)          // 2048

#define WQ_ELEMS   (NL*DM*DM)          // 7,077,888
#define W1_ELEMS   (NL*DM*DFF)         // 28,311,552
#define WOUT_ELEMS (DM*NV)             // 76,996,608
// offsets into the packed weight-plane buffers
#define OWQ   0
#define OWK   (OWQ + WQ_ELEMS)
#define OWV   (OWK + WQ_ELEMS)
#define OWO   (OWV + WQ_ELEMS)
#define OW1   (OWO + WQ_ELEMS)
#define OW2   (OW1 + W1_ELEMS)
#define OWOUT (OW2 + W1_ELEMS)
#define WTOT  (OWOUT + WOUT_ELEMS)     // 161,931,264

// ---------------- scratch (device globals; no allocs allowed) ----------------
__device__ float g_x  [MROWS*DM];
__device__ float g_q  [MROWS*DM];
__device__ float g_k  [MROWS*DM];
__device__ float g_v  [MROWS*DM];
__device__ float g_rowloss[MROWS];
// bf16 hi/lo planes
__device__ __nv_bfloat16 g_hhi [MROWS*DM];
__device__ __nv_bfloat16 g_hlo [MROWS*DM];
__device__ __nv_bfloat16 g_athi[MROWS*DM];
__device__ __nv_bfloat16 g_atlo[MROWS*DM];
__device__ __nv_bfloat16 g_ffhi[MROWS*DFF];
__device__ __nv_bfloat16 g_fflo[MROWS*DFF];
__device__ __nv_bfloat16 g_whi[WTOT];
__device__ __nv_bfloat16 g_wlo[WTOT];

// ---------------- helpers ----------------
__device__ __forceinline__ void split_bf16(float x, __nv_bfloat16& hi, __nv_bfloat16& lo) {
    hi = __float2bfloat16(x);
    lo = __float2bfloat16(x - __bfloat162float(hi));
}
__device__ __forceinline__ void mma_bf16(float* d, const unsigned* a, const unsigned* b) {
    asm volatile(
        "mma.sync.aligned.m16n8k16.row.col.f32.bf16.bf16.f32 "
        "{%0,%1,%2,%3}, {%4,%5,%6,%7}, {%8,%9}, {%0,%1,%2,%3};\n"
        : "+f"(d[0]), "+f"(d[1]), "+f"(d[2]), "+f"(d[3])
        : "r"(a[0]), "r"(a[1]), "r"(a[2]), "r"(a[3]), "r"(b[0]), "r"(b[1]));
}
__device__ __forceinline__ void ldsm4(unsigned addr, unsigned& r0, unsigned& r1,
                                      unsigned& r2, unsigned& r3) {
    asm volatile("ldmatrix.sync.aligned.m8n8.x4.shared.b16 {%0,%1,%2,%3}, [%4];"
                 : "=r"(r0), "=r"(r1), "=r"(r2), "=r"(r3) : "r"(addr));
}
__device__ __forceinline__ void ldsm4t(unsigned addr, unsigned& r0, unsigned& r1,
                                       unsigned& r2, unsigned& r3) {
    asm volatile("ldmatrix.sync.aligned.m8n8.x4.trans.shared.b16 {%0,%1,%2,%3}, [%4];"
                 : "=r"(r0), "=r"(r1), "=r"(r2), "=r"(r3) : "r"(addr));
}
__device__ __forceinline__ void cpasync16(unsigned dst, const void* src, int srcbytes) {
    asm volatile("cp.async.cg.shared.global [%0], [%1], 16, %2;"
                 :: "r"(dst), "l"(src), "r"(srcbytes));
}

// ---------------- weight split: fp32 -> (hi,lo) bf16 planes ------------------
__global__ void split_kernel(const float* __restrict__ src,
                             __nv_bfloat16* __restrict__ hi,
                             __nv_bfloat16* __restrict__ lo, int n)
{
    for (int i = blockIdx.x * blockDim.x + threadIdx.x; i < n;
         i += gridDim.x * blockDim.x) {
        float x = src[i];
        __nv_bfloat16 h = __float2bfloat16(x);
        hi[i] = h;
        lo[i] = __float2bfloat16(x - __bfloat162float(h));
    }
}

// ---------------- embedding + sinusoidal positional encoding ----------------
__global__ void embed_kernel(const int* __restrict__ idx,
                             const float* __restrict__ emb,
                             float* __restrict__ x)
{
    int i = blockIdx.x * blockDim.x + threadIdx.x;
    if (i >= MROWS * DM) return;
    int d  = i % DM;
    int bt = i / DM;
    int t  = bt % NT;
    int tok = idx[bt];
    int ii = d & ~1;
    float div = expf(-(float)ii * (logf(10000.0f) / (float)DM));
    float ang = (float)t * div;
    float pe  = (d & 1) ? cosf(ang) : sinf(ang);
    x[i] = emb[(size_t)tok * DM + d] + pe;
}

// ---------------- layernorm -> (hi,lo) bf16 planes ---------------------------
__global__ void ln_kernel(const float* __restrict__ x,
                          const float* __restrict__ s,
                          const float* __restrict__ b,
                          __nv_bfloat16* __restrict__ yhi,
                          __nv_bfloat16* __restrict__ ylo)
{
    int row = blockIdx.x;
    int tid = threadIdx.x;
    const float* xr = x + (size_t)row * DM;

    float v0 = xr[tid], v1 = xr[tid + 256], v2 = xr[tid + 512];

    __shared__ float red[256];
    red[tid] = v0 + v1 + v2; __syncthreads();
    for (int o = 128; o > 0; o >>= 1) {
        if (tid < o) red[tid] += red[tid + o];
        __syncthreads();
    }
    float mu = red[0] * (1.0f / DM);
    __syncthreads();

    float d0 = v0 - mu, d1 = v1 - mu, d2 = v2 - mu;
    red[tid] = d0*d0 + d1*d1 + d2*d2; __syncthreads();
    for (int o = 128; o > 0; o >>= 1) {
        if (tid < o) red[tid] += red[tid + o];
        __syncthreads();
    }
    float var = red[0] * (1.0f / DM);
    float r = rsqrtf(var + 1e-5f);

    size_t base = (size_t)row * DM;
#pragma unroll
    for (int j = 0; j < 3; j++) {
        int c = tid + j * 256;
        float dv = (j == 0 ? d0 : j == 1 ? d1 : d2);
        float y = dv * r * s[c] + b[c];
        split_bf16(y, yhi[base + c], ylo[base + c]);
    }
}

// ---------------- split-bf16 tensor-core GEMM --------------------------------
// C = epilogue(A @ B + bias [+ R]); A,B given as (hi,lo) bf16 planes.
// EPI: 0 = +bias (fp32 C) ; 2 = +bias + residual R (fp32 C, R may alias C)
//      3 = relu(+bias) -> split written to (Chi,Clo)
// Block tile 128 x BN, BK=16, 256 threads (8 warps). blockIdx.z: fused QKV.
struct BPtrs {
    const __nv_bfloat16* Bhi[3];
    const __nv_bfloat16* Blo[3];
    float*               C[3];
    const float*         bias[3];
};

template<int BN, int MT, int NTT, int EPI>
__global__ void __launch_bounds__(256)
bmma_gemm(const __nv_bfloat16* __restrict__ Ahi,
          const __nv_bfloat16* __restrict__ Alo,
          BPtrs p, const float* __restrict__ R,
          __nv_bfloat16* __restrict__ Chi, __nv_bfloat16* __restrict__ Clo,
          int M, int N, int K)
{
    constexpr int BM = 128, BK = 16;
    constexpr int AP = 24;          // As row stride (bf16)
    constexpr int BP = BN + 8;      // Bs row stride (bf16)
    constexpr int WCOLS = BN / (NTT * 8);

    __shared__ __nv_bfloat16 As[2][2][BM * AP];
    __shared__ __nv_bfloat16 Bs[2][2][BK * BP];

    const int z = blockIdx.z;
    const __nv_bfloat16* __restrict__ Bhi  = p.Bhi[z];
    const __nv_bfloat16* __restrict__ Blo  = p.Blo[z];
    float*               __restrict__ C    = p.C[z];
    const float*         __restrict__ bias = p.bias[z];

    const int tid  = threadIdx.x;
    const int lane = tid & 31;
    const int w    = tid >> 5;
    const int wm   = w / WCOLS;
    const int wn   = w % WCOLS;
    const int row0 = blockIdx.y * BM;
    const int col0 = blockIdx.x * BN;
    const int grp  = lane >> 2;
    const int tig  = lane & 3;
    const int mB   = wm * MT * 16;
    const int nB   = wn * NTT * 8;

    float acc[MT][NTT][4];
#pragma unroll
    for (int i = 0; i < MT; i++)
#pragma unroll
        for (int j = 0; j < NTT; j++)
#pragma unroll
            for (int q = 0; q < 4; q++) acc[i][j][q] = 0.0f;

    auto load_stage = [&](int buf, int k0) {
        // A planes: 256 chunks of 16B each (8 bf16) per plane
        {
            int m  = tid >> 1;
            int kq = (tid & 1) * 8;
            unsigned doff = (unsigned)(m * AP + kq) * 2;
            size_t goff = (size_t)(row0 + m) * K + k0 + kq;
            cpasync16((unsigned)__cvta_generic_to_shared(&As[buf][0][0]) + doff, Ahi + goff, 16);
            cpasync16((unsigned)__cvta_generic_to_shared(&As[buf][1][0]) + doff, Alo + goff, 16);
        }
        // B planes: 2*BN chunks per plane
        constexpr int BCH = 2 * BN;          // 128 (BN=64) or 256 (BN=128)
        if (BCH == 256 || tid < BCH) {
            int kk = tid / (BN / 8);
            int nq = (tid % (BN / 8)) * 8;
            int gc = col0 + nq;
            int ok = (gc < N) ? 16 : 0;
            int gcs = (gc < N) ? gc : (N - 8);
            unsigned doff = (unsigned)(kk * BP + nq) * 2;
            size_t goff = (size_t)(k0 + kk) * N + gcs;
            cpasync16((unsigned)__cvta_generic_to_shared(&Bs[buf][0][0]) + doff, Bhi + goff, ok);
            cpasync16((unsigned)__cvta_generic_to_shared(&Bs[buf][1][0]) + doff, Blo + goff, ok);
        }
    };

    const int arow  = (lane & 15);
    const int acolb = (lane >> 4) * 8;
    const int brow  = (lane & 7) + ((lane >> 3) & 1) * 8;
    const int bcolq = (lane >> 4) * 8;

    auto compute_stage = [&](int buf) {
        unsigned ahib = (unsigned)__cvta_generic_to_shared(&As[buf][0][0]);
        unsigned alob = (unsigned)__cvta_generic_to_shared(&As[buf][1][0]);
        unsigned bhib = (unsigned)__cvta_generic_to_shared(&Bs[buf][0][0]);
        unsigned blob = (unsigned)__cvta_generic_to_shared(&Bs[buf][1][0]);

        unsigned ahi[MT][4], alo[MT][4];
#pragma unroll
        for (int mt = 0; mt < MT; mt++) {
            unsigned off = (unsigned)((mB + mt * 16 + arow) * AP + acolb) * 2;
            ldsm4(ahib + off, ahi[mt][0], ahi[mt][1], ahi[mt][2], ahi[mt][3]);
            ldsm4(alob + off, alo[mt][0], alo[mt][1], alo[mt][2], alo[mt][3]);
        }
        unsigned bhi[NTT][2], blo[NTT][2];
#pragma unroll
        for (int nt2 = 0; nt2 < NTT / 2; nt2++) {
            unsigned off = (unsigned)(brow * BP + nB + nt2 * 16 + bcolq) * 2;
            ldsm4t(bhib + off, bhi[nt2*2][0], bhi[nt2*2][1], bhi[nt2*2+1][0], bhi[nt2*2+1][1]);
            ldsm4t(blob + off, blo[nt2*2][0], blo[nt2*2][1], blo[nt2*2+1][0], blo[nt2*2+1][1]);
        }
#pragma unroll
        for (int mt = 0; mt < MT; mt++)
#pragma unroll
            for (int nt = 0; nt < NTT; nt++) {
                mma_bf16(acc[mt][nt], ahi[mt], blo[nt]);
                mma_bf16(acc[mt][nt], alo[mt], bhi[nt]);
                mma_bf16(acc[mt][nt], ahi[mt], bhi[nt]);
            }
    };

    const int NKIT = K / BK;
    load_stage(0, 0);
    asm volatile("cp.async.commit_group;");

    for (int it = 0; it < NKIT; ++it) {
        if (it + 1 < NKIT) {
            load_stage((it + 1) & 1, (it + 1) * BK);
            asm volatile("cp.async.commit_group;");
            asm volatile("cp.async.wait_group 1;");
        } else {
            asm volatile("cp.async.wait_group 0;");
        }
        __syncthreads();
        compute_stage(it & 1);
        __syncthreads();
    }

    // epilogue
#pragma unroll
    for (int mt = 0; mt < MT; mt++) {
        int r = row0 + mB + mt * 16 + grp;
#pragma unroll
        for (int nt = 0; nt < NTT; nt++) {
            int c = col0 + nB + nt * 8 + tig * 2;
            if (c < N) {
                float x0 = acc[mt][nt][0], x1 = acc[mt][nt][1];
                float x2 = acc[mt][nt][2], x3 = acc[mt][nt][3];
                if (bias) {
                    float b0 = bias[c], b1 = bias[c + 1];
                    x0 += b0; x1 += b1; x2 += b0; x3 += b1;
                }
                if (EPI == 3) {
                    x0 = fmaxf(x0, 0.f); x1 = fmaxf(x1, 0.f);
                    x2 = fmaxf(x2, 0.f); x3 = fmaxf(x3, 0.f);
                    size_t i0 = (size_t) r      * N + c;
                    size_t i1 = (size_t)(r + 8) * N + c;
                    split_bf16(x0, Chi[i0    ], Clo[i0    ]);
                    split_bf16(x1, Chi[i0 + 1], Clo[i0 + 1]);
                    split_bf16(x2, Chi[i1    ], Clo[i1    ]);
                    split_bf16(x3, Chi[i1 + 1], Clo[i1 + 1]);
                } else {
                    if (EPI == 2) {
                        x0 += R[(size_t) r      * N + c    ];
                        x1 += R[(size_t) r      * N + c + 1];
                        x2 += R[(size_t)(r + 8) * N + c    ];
                        x3 += R[(size_t)(r + 8) * N + c + 1];
                    }
                    C[(size_t) r      * N + c    ] = x0;
                    C[(size_t) r      * N + c + 1] = x1;
                    C[(size_t)(r + 8) * N + c    ] = x2;
                    C[(size_t)(r + 8) * N + c + 1] = x3;
                }
            }
        }
    }
}

// ---------------- causal attention: one warp per query row -------------------
__global__ void attn_kernel(const float* __restrict__ q,
                            const float* __restrict__ k,
                            const float* __restrict__ v,
                            __nv_bfloat16* __restrict__ ohi,
                            __nv_bfloat16* __restrict__ olo)
{
    int w    = (blockIdx.x * blockDim.x + threadIdx.x) >> 5;
    int lane = threadIdx.x & 31;
    int t = w % NT;
    int h = (w / NT) % NH;
    int b = w / (NT * NH);

    size_t qb = ((size_t)(b * NT + t) * NH + h) * DH;
    float q0 = q[qb + lane];
    float q1 = q[qb + lane + 32];

    float m = -INFINITY, l = 0.0f, o0 = 0.0f, o1 = 0.0f;
    const float scale = 0.125f;

    for (int s = 0; s <= t; s++) {
        size_t kb = ((size_t)(b * NT + s) * NH + h) * DH;
        float d = q0 * k[kb + lane] + q1 * k[kb + lane + 32];
#pragma unroll
        for (int off = 16; off > 0; off >>= 1)
            d += __shfl_xor_sync(0xffffffff, d, off);
        d *= scale;

        float mn = fmaxf(m, d);
        float c  = __expf(m - mn);
        float p  = __expf(d - mn);
        l  = l * c + p;
        o0 = o0 * c + p * v[kb + lane];
        o1 = o1 * c + p * v[kb + lane + 32];
        m = mn;
    }
    float inv = 1.0f / l;
    split_bf16(o0 * inv, ohi[qb + lane     ], olo[qb + lane     ]);
    split_bf16(o1 * inv, ohi[qb + lane + 32], olo[qb + lane + 32]);
}

// ---------------- per-row NLL loss ----------------
__global__ void loss_row_kernel(const float* __restrict__ logits,
                                const int* __restrict__ tgt,
                                float* __restrict__ rowloss)
{
    int r   = blockIdx.x;
    int tid = threadIdx.x;
    const float* lr = logits + (size_t)r * NV;

    float m = -INFINITY, s = 0.0f;
    for (int i = tid; i < NV; i += 256) {
        float x = lr[i];
        if (x > m) { s = s * __expf(m - x) + 1.0f; m = x; }
        else       { s += __expf(x - m); }
    }
    __shared__ float sm[256], ss[256];
    sm[tid] = m; ss[tid] = s; __syncthreads();
    for (int o = 128; o > 0; o >>= 1) {
        if (tid < o) {
            float m2 = sm[tid + o], s2 = ss[tid + o];
            float mn = fmaxf(sm[tid], m2);
            ss[tid] = ss[tid] * __expf(sm[tid] - mn) + s2 * __expf(m2 - mn);
            sm[tid] = mn;
        }
        __syncthreads();
    }
    if (tid == 0) {
        float lse = sm[0] + logf(ss[0]);
        rowloss[r] = lse - lr[tgt[r]];
    }
}

__global__ void loss_reduce_kernel(const float* __restrict__ rowloss,
                                   float* __restrict__ out)
{
    __shared__ float sh[256];
    int tid = threadIdx.x;
    float s = 0.0f;
    for (int i = tid; i < MROWS; i += 256) s += rowloss[i];
    sh[tid] = s; __syncthreads();
    for (int o = 128; o > 0; o >>= 1) {
        if (tid < o) sh[tid] += sh[tid + o];
        __syncthreads();
    }
    if (tid == 0) out[0] = sh[0] * (1.0f / MROWS);
}

// ---------------- host driver ----------------
extern "C" void kernel_launch(void* const* d_in, const int* in_sizes, int n_in,
                              void* d_out, int out_size)
{
    const int*   idx     = (const int*)  d_in[0];
    const int*   targets = (const int*)  d_in[1];
    const float* emb     = (const float*)d_in[2];
    const float* wq      = (const float*)d_in[3];
    const float* wk      = (const float*)d_in[4];
    const float* wv      = (const float*)d_in[5];
    const float* wo      = (const float*)d_in[6];
    const float* bo      = (const float*)d_in[7];
    const float* ln1_s   = (const float*)d_in[8];
    const float* ln1_b   = (const float*)d_in[9];
    const float* ln2_s   = (const float*)d_in[10];
    const float* ln2_b   = (const float*)d_in[11];
    const float* w1      = (const float*)d_in[12];
    const float* b1      = (const float*)d_in[13];
    const float* w2      = (const float*)d_in[14];
    const float* b2      = (const float*)d_in[15];
    const float* lnf_s   = (const float*)d_in[16];
    const float* lnf_b   = (const float*)d_in[17];
    const float* w_out   = (const float*)d_in[18];
    const float* b_out   = (const float*)d_in[19];
    float* out = (float*)d_out;

    float *x, *q, *k, *v, *rl;
    __nv_bfloat16 *hhi, *hlo, *athi, *atlo, *ffhi, *fflo, *whi, *wlo;
    cudaGetSymbolAddress((void**)&x,    g_x);
    cudaGetSymbolAddress((void**)&q,    g_q);
    cudaGetSymbolAddress((void**)&k,    g_k);
    cudaGetSymbolAddress((void**)&v,    g_v);
    cudaGetSymbolAddress((void**)&rl,   g_rowloss);
    cudaGetSymbolAddress((void**)&hhi,  g_hhi);
    cudaGetSymbolAddress((void**)&hlo,  g_hlo);
    cudaGetSymbolAddress((void**)&athi, g_athi);
    cudaGetSymbolAddress((void**)&atlo, g_atlo);
    cudaGetSymbolAddress((void**)&ffhi, g_ffhi);
    cudaGetSymbolAddress((void**)&fflo, g_fflo);
    cudaGetSymbolAddress((void**)&whi,  g_whi);
    cudaGetSymbolAddress((void**)&wlo,  g_wlo);

    // split all weights into bf16 hi/lo planes (streaming, ~0.2 ms)
    split_kernel<<<4096, 256>>>(wq,    whi + OWQ,   wlo + OWQ,   WQ_ELEMS);
    split_kernel<<<4096, 256>>>(wk,    whi + OWK,   wlo + OWK,   WQ_ELEMS);
    split_kernel<<<4096, 256>>>(wv,    whi + OWV,   wlo + OWV,   WQ_ELEMS);
    split_kernel<<<4096, 256>>>(wo,    whi + OWO,   wlo + OWO,   WQ_ELEMS);
    split_kernel<<<4096, 256>>>(w1,    whi + OW1,   wlo + OW1,   W1_ELEMS);
    split_kernel<<<4096, 256>>>(w2,    whi + OW2,   wlo + OW2,   W1_ELEMS);
    split_kernel<<<8192, 256>>>(w_out, whi + OWOUT, wlo + OWOUT, WOUT_ELEMS);

    embed_kernel<<<(MROWS * DM + 255) / 256, 256>>>(idx, emb, x);

    for (int l = 0; l < NL; l++) {
        size_t oqkv = (size_t)l * DM * DM;
        size_t offn = (size_t)l * DM * DFF;

        // h = LN1(x) -> planes
        ln_kernel<<<MROWS, 256>>>(x, ln1_s + l * DM, ln1_b + l * DM, hhi, hlo);

        // q,k,v = h @ w{q,k,v}
        {
            BPtrs p;
            p.Bhi[0] = whi + OWQ + oqkv; p.Blo[0] = wlo + OWQ + oqkv;
            p.Bhi[1] = whi + OWK + oqkv; p.Blo[1] = wlo + OWK + oqkv;
            p.Bhi[2] = whi + OWV + oqkv; p.Blo[2] = wlo + OWV + oqkv;
            p.C[0] = q; p.C[1] = k; p.C[2] = v;
            p.bias[0] = p.bias[1] = p.bias[2] = nullptr;
            bmma_gemm<64, 2, 4, 0><<<dim3(DM / 64, MROWS / 128, 3), 256>>>(
                hhi, hlo, p, nullptr, nullptr, nullptr, MROWS, DM, DM);
        }

        // att = causal_softmax(q k^T / 8) v -> planes
        attn_kernel<<<(MROWS * NH) / 8, 256>>>(q, k, v, athi, atlo);

        // x = x + att @ wo + bo
        {
            BPtrs p = {};
            p.Bhi[0] = whi + OWO + oqkv; p.Blo[0] = wlo + OWO + oqkv;
            p.C[0] = x; p.bias[0] = bo + l * DM;
            bmma_gemm<64, 2, 4, 2><<<dim3(DM / 64, MROWS / 128, 1), 256>>>(
                athi, atlo, p, x, nullptr, nullptr, MROWS, DM, DM);
        }

        // h = LN2(x) -> planes
        ln_kernel<<<MROWS, 256>>>(x, ln2_s + l * DM, ln2_b + l * DM, hhi, hlo);

        // ff = relu(h @ w1 + b1) -> planes
        {
            BPtrs p = {};
            p.Bhi[0] = whi + OW1 + offn; p.Blo[0] = wlo + OW1 + offn;
            p.bias[0] = b1 + l * DFF;
            bmma_gemm<128, 4, 4, 3><<<dim3(DFF / 128, MROWS / 128, 1), 256>>>(
                hhi, hlo, p, nullptr, ffhi, fflo, MROWS, DFF, DM);
        }

        // x = x + ff @ w2 + b2
        {
            BPtrs p = {};
            p.Bhi[0] = whi + OW2 + offn; p.Blo[0] = wlo + OW2 + offn;
            p.C[0] = x; p.bias[0] = b2 + l * DM;
            bmma_gemm<64, 2, 4, 2><<<dim3(DM / 64, MROWS / 128, 1), 256>>>(
                ffhi, fflo, p, x, nullptr, nullptr, MROWS, DM, DFF);
        }
    }

    // h = LNf(x) -> planes
    ln_kernel<<<MROWS, 256>>>(x, lnf_s, lnf_b, hhi, hlo);

    // logits = h @ w_out + b_out
    {
        BPtrs p = {};
        p.Bhi[0] = whi + OWOUT; p.Blo[0] = wlo + OWOUT;
        p.C[0] = out; p.bias[0] = b_out;
        bmma_gemm<128, 4, 4, 0><<<dim3((NV + 127) / 128, MROWS / 128, 1), 256>>>(
            hhi, hlo, p, nullptr, nullptr, nullptr, MROWS, NV, DM);
    }

    // loss
    loss_row_kernel<<<MROWS, 256>>>(out, targets, rl);
    loss_reduce_kernel<<<1, 256>>>(rl, out + (size_t)MROWS * NV);
}